// round 1
// baseline (speedup 1.0000x reference)
#include <cuda_runtime.h>
#include <math.h>

#define L 256
#define B 32
#define C 64
#define LB (L * B)           // 8192
#define LBC (LB * C)         // 524288
#define DMAX 20
#define TL 64
#define NBUCKET 256

// Scratch (allocation-free rule: __device__ globals)
__device__ float g_fmp[LBC];
__device__ float g_fmf[LBC];
__device__ float g_smp[LBC];
__device__ float g_smf[LBC];
__device__ float g_buckets[NBUCKET];

// ---------------------------------------------------------------------------
// Kernel 1: Gaussian-decay message passing as a +/-DMAX stencil.
// past[s,i] = exp(-(s-i)^2/8)/max(s,1) for i<s ; fut analogous for i>s.
// exp(-d^2/8) < 2e-22 for d>20 -> truncation is exact at fp32.
// grid: (L/TL, B, 2)  z: 0 -> f, 1 -> s. 256 threads.
// Block (0,0,0) also zeroes the loss buckets.
// ---------------------------------------------------------------------------
__global__ void msg_kernel(const float* __restrict__ f,
                           const float* __restrict__ s) {
    __shared__ float tile[(TL + 2 * DMAX) * C];   // 104*64*4 = 26.6 KB

    const int tid = threadIdx.x;
    const int l0  = blockIdx.x * TL;
    const int b   = blockIdx.y;
    const int tz  = blockIdx.z;

    if (blockIdx.x == 0 && blockIdx.y == 0 && blockIdx.z == 0 && tid < NBUCKET)
        g_buckets[tid] = 0.0f;

    const float* __restrict__ x  = (tz == 0) ? f : s;
    float* __restrict__ mp = (tz == 0) ? g_fmp : g_smp;
    float* __restrict__ mf = (tz == 0) ? g_fmf : g_smf;

    // load halo'd tile, zero-padded out of range
    for (int i = tid; i < (TL + 2 * DMAX) * C; i += blockDim.x) {
        int row = i >> 6;
        int c   = i & 63;
        int lg  = l0 - DMAX + row;
        tile[i] = (lg >= 0 && lg < L) ? x[((size_t)lg * B + b) * C + c] : 0.0f;
    }
    __syncthreads();

    float wv[DMAX + 1];
#pragma unroll
    for (int d = 1; d <= DMAX; ++d) wv[d] = expf(-(float)(d * d) * 0.125f);

    const int c  = tid & 63;
    const int lq = tid >> 6;   // 0..3

    for (int j = lq; j < TL; j += 4) {
        const int l = l0 + j;
        float ap = 0.0f, af = 0.0f;
#pragma unroll
        for (int d = 1; d <= DMAX; ++d) {
            ap += wv[d] * tile[(j + DMAX - d) * C + c];
            af += wv[d] * tile[(j + DMAX + d) * C + c];
        }
        const size_t o = ((size_t)l * B + b) * C + c;
        mp[o] = ap / (float)max(l, 1);
        mf[o] = af / (float)max(L - 1 - l, 1);
    }
}

// ---------------------------------------------------------------------------
// Per-matrix streaming: single pass over a 64x64 matrix computing
//   out_row[r] += sum_c M[r][c] * vcol[c]      (M @ vcol)
//   out_col[c] += sum_r M[r][c] * vrow[r]      (M^T @ vrow)
// 8 warps, warp w owns rows [8w, 8w+8). Lanes 0-15 even rows / 16-31 odd
// rows of each pair; float4 loads -> fully coalesced 512B per warp-load.
// ---------------------------------------------------------------------------
__device__ __forceinline__ void procmat(const float* __restrict__ M,
                                        const float* __restrict__ vcol,
                                        const float* __restrict__ vrow,
                                        float* out_row, float* out_col,
                                        int tid) {
    const int w    = tid >> 5;
    const int lane = tid & 31;
    const int half = lane >> 4;   // 0 or 1
    const int li   = lane & 15;   // col group 0..15

    const float4 vc = *(const float4*)(vcol + li * 4);
    float4 cacc = make_float4(0.f, 0.f, 0.f, 0.f);

#pragma unroll
    for (int rp = 0; rp < 4; ++rp) {
        const int r = (w << 3) + (rp << 1) + half;
        const float4 m = *(const float4*)(M + (r << 6) + (li << 2));

        // row dot (reduce over 16 lanes of this half)
        float d = m.x * vc.x + m.y * vc.y + m.z * vc.z + m.w * vc.w;
        d += __shfl_xor_sync(0xffffffffu, d, 8);
        d += __shfl_xor_sync(0xffffffffu, d, 4);
        d += __shfl_xor_sync(0xffffffffu, d, 2);
        d += __shfl_xor_sync(0xffffffffu, d, 1);
        if (li == 0) atomicAdd(&out_row[r], d);

        // column accumulation
        const float vr = vrow[r];
        cacc.x += m.x * vr; cacc.y += m.y * vr;
        cacc.z += m.z * vr; cacc.w += m.w * vr;
    }

    // fold odd-row half into even-row half (same columns)
    cacc.x += __shfl_down_sync(0xffffffffu, cacc.x, 16);
    cacc.y += __shfl_down_sync(0xffffffffu, cacc.y, 16);
    cacc.z += __shfl_down_sync(0xffffffffu, cacc.z, 16);
    cacc.w += __shfl_down_sync(0xffffffffu, cacc.w, 16);
    if (half == 0) {
        atomicAdd(&out_col[li * 4 + 0], cacc.x);
        atomicAdd(&out_col[li * 4 + 1], cacc.y);
        atomicAdd(&out_col[li * 4 + 2], cacc.z);
        atomicAdd(&out_col[li * 4 + 3], cacc.w);
    }
}

// warp-level softmax + CE over 64 logits (lane holds j=lane and j=lane+32).
// If outp != nullptr also writes softmax probs. Returns (lse - v[label]).
__device__ __forceinline__ float warp_softmax_ce(float v0, float v1, int lane,
                                                 int label, float* outp) {
    float m = fmaxf(v0, v1);
#pragma unroll
    for (int o = 16; o; o >>= 1) m = fmaxf(m, __shfl_xor_sync(0xffffffffu, m, o));
    float e0 = __expf(v0 - m), e1 = __expf(v1 - m);
    float sum = e0 + e1;
#pragma unroll
    for (int o = 16; o; o >>= 1) sum += __shfl_xor_sync(0xffffffffu, sum, o);
    if (outp) {
        const float inv = 1.0f / sum;
        outp[lane]      = e0 * inv;
        outp[lane + 32] = e1 * inv;
    }
    const float lse = m + __logf(sum);
    const float vl  = __shfl_sync(0xffffffffu, (label < 32) ? v0 : v1, label & 31);
    return lse - vl;
}

// ---------------------------------------------------------------------------
// Kernel 2: one CTA per (l,b). Streams the 5 matrices (80 KB) once,
// builds next_f/next_s, writes softmax outputs and loss partials.
// ---------------------------------------------------------------------------
__global__ void __launch_bounds__(256, 8)
main_kernel(const float* __restrict__ f,  const float* __restrict__ s,
            const float* __restrict__ fs, const float* __restrict__ ff,
            const float* __restrict__ ss, const float* __restrict__ fs_t,
            const float* __restrict__ sf_t,
            const int* __restrict__ f_lab, const int* __restrict__ s_lab,
            float* __restrict__ out) {
    const int blk = blockIdx.x;                 // l*B + b
    const size_t voff = (size_t)blk * C;
    const size_t moff = (size_t)blk * (C * C);
    const int tid = threadIdx.x;

    __shared__ __align__(16) float sf0[C], ss0[C];
    __shared__ __align__(16) float v_fmp[C], v_fmf[C], v_smp[C], v_smf[C];
    __shared__ __align__(16) float v_fW[C], v_sW[C];
    __shared__ __align__(16) float accf[C], accs[C];
    __shared__ float lossAcc;

    if (tid < C) {
        const float fv = f[voff + tid];
        const float sv = s[voff + tid];
        sf0[tid] = fv;          ss0[tid] = sv;
        v_fW[tid] = 0.5f * fv;  v_sW[tid] = 0.5f * sv;           // W_S
        v_fmp[tid] = 0.5f * g_fmp[voff + tid];                    // W_T
        v_fmf[tid] = 0.5f * g_fmf[voff + tid];
        v_smp[tid] = 0.5f * g_smp[voff + tid];
        v_smf[tid] = 0.5f * g_smf[voff + tid];
        accf[tid] = 0.0f;       accs[tid] = 0.0f;
    }
    if (tid == 0) lossAcc = 0.0f;
    __syncthreads();

    // next_f += ff @ (wT*f_mf)        ; next_f += ff^T @ (wT*f_mp)
    procmat(ff   + moff, v_fmf, v_fmp, accf, accf, tid);
    // next_s += ss @ (wT*s_mf)        ; next_s += ss^T @ (wT*s_mp)
    procmat(ss   + moff, v_smf, v_smp, accs, accs, tid);
    // next_f += fs @ (wS*s)           ; next_s += fs^T @ (wS*f)
    procmat(fs   + moff, v_sW,  v_fW,  accf, accs, tid);
    // next_f += fs_t @ (wT*s_mf)      ; next_s += fs_t^T @ (wT*f_mp)
    procmat(fs_t + moff, v_smf, v_fmp, accf, accs, tid);
    // next_s += sf_t @ (wT*f_mf)      ; next_f += sf_t^T @ (wT*s_mp)
    procmat(sf_t + moff, v_fmf, v_smp, accs, accf, tid);
    __syncthreads();

    const int w = tid >> 5, lane = tid & 31;
    if (w == 0) {
        const int lab = f_lab[blk];
        const float a0 = sf0[lane], a1 = sf0[lane + 32];
        const float ce0 = warp_softmax_ce(a0, a1, lane, lab, nullptr);
        const float n0 = a0 + accf[lane], n1 = a1 + accf[lane + 32];
        const float ce1 = warp_softmax_ce(n0, n1, lane, lab, out + voff);
        if (lane == 0) atomicAdd(&lossAcc, ce0 + ce1);
    } else if (w == 1) {
        const int lab = s_lab[blk];
        const float a0 = ss0[lane], a1 = ss0[lane + 32];
        const float ce0 = warp_softmax_ce(a0, a1, lane, lab, nullptr);
        const float n0 = a0 + accs[lane], n1 = a1 + accs[lane + 32];
        const float ce1 = warp_softmax_ce(n0, n1, lane, lab, out + (size_t)LBC + voff);
        if (lane == 0) atomicAdd(&lossAcc, ce0 + ce1);
    }
    __syncthreads();
    if (tid == 0) atomicAdd(&g_buckets[blk & (NBUCKET - 1)], lossAcc);
}

// ---------------------------------------------------------------------------
// Kernel 3: deterministic bucket reduction -> loss scalar.
// loss = (sum of 4 CE sums) / (L*B)    (each _ce is a mean over L*B rows)
// ---------------------------------------------------------------------------
__global__ void loss_finalize(float* __restrict__ out_loss) {
    __shared__ float sm[NBUCKET];
    const int t = threadIdx.x;
    sm[t] = g_buckets[t];
    __syncthreads();
    for (int sct = NBUCKET / 2; sct > 0; sct >>= 1) {
        if (t < sct) sm[t] += sm[t + sct];
        __syncthreads();
    }
    if (t == 0) out_loss[0] = sm[0] * (1.0f / (float)LB);
}

// ---------------------------------------------------------------------------
extern "C" void kernel_launch(void* const* d_in, const int* in_sizes, int n_in,
                              void* d_out, int out_size) {
    const float* f    = (const float*)d_in[0];
    const float* s    = (const float*)d_in[1];
    const float* fs   = (const float*)d_in[2];
    const float* ff   = (const float*)d_in[3];
    const float* ss   = (const float*)d_in[4];
    const float* fs_t = (const float*)d_in[5];
    const float* sf_t = (const float*)d_in[6];
    const int* f_lab  = (const int*)d_in[7];
    const int* s_lab  = (const int*)d_in[8];
    float* out = (float*)d_out;

    dim3 g1(L / TL, B, 2);
    msg_kernel<<<g1, 256>>>(f, s);
    main_kernel<<<LB, 256>>>(f, s, fs, ff, ss, fs_t, sf_t, f_lab, s_lab, out);
    loss_finalize<<<1, NBUCKET>>>(out + (size_t)2 * LBC);
}

// round 2
// speedup vs baseline: 1.1470x; 1.1470x over previous
#include <cuda_runtime.h>
#include <math.h>

#define L 256
#define B 32
#define C 64
#define LB (L * B)           // 8192
#define LBC (LB * C)         // 524288
#define DMAX 20
#define TL 32                // rows per msg block
#define RPT 8                // rows per thread in msg kernel
#define NBUCKET 256

// Scratch (allocation-free rule: __device__ globals)
__device__ float g_fmp[LBC];
__device__ float g_fmf[LBC];
__device__ float g_smp[LBC];
__device__ float g_smf[LBC];
__device__ float g_buckets[NBUCKET];

// ---------------------------------------------------------------------------
// Kernel 1: Gaussian-decay message passing as a +/-DMAX stencil.
// exp(-d^2/8) < 2e-22 for d>20 -> truncation exact at fp32.
// grid: (L/TL, B, 2)  z: 0 -> f, 1 -> s. 256 threads.
// Each thread owns one channel c and RPT=8 consecutive rows; every smem
// input value is loaded once and feeds up to 8 static-weight FMAs
// (16 independent accumulator chains per thread for ILP).
// ---------------------------------------------------------------------------
__global__ void __launch_bounds__(256) msg_kernel(const float* __restrict__ f,
                                                  const float* __restrict__ s) {
    __shared__ float tile[(TL + 2 * DMAX) * C];   // 72*64*4 = 18.4 KB

    const int tid = threadIdx.x;
    const int l0  = blockIdx.x * TL;
    const int b   = blockIdx.y;
    const int tz  = blockIdx.z;

    if (blockIdx.x == 0 && blockIdx.y == 0 && blockIdx.z == 0 && tid < NBUCKET)
        g_buckets[tid] = 0.0f;

    const float* __restrict__ x  = (tz == 0) ? f : s;
    float* __restrict__ mp = (tz == 0) ? g_fmp : g_smp;
    float* __restrict__ mf = (tz == 0) ? g_fmf : g_smf;

    // load halo'd tile, zero-padded out of range
#pragma unroll
    for (int i = tid; i < (TL + 2 * DMAX) * C; i += 256) {
        int row = i >> 6;
        int c   = i & 63;
        int lg  = l0 - DMAX + row;
        tile[i] = (lg >= 0 && lg < L) ? x[((size_t)lg * B + b) * C + c] : 0.0f;
    }
    __syncthreads();

    float wv[DMAX + 1];
    wv[0] = 0.0f;
#pragma unroll
    for (int d = 1; d <= DMAX; ++d) wv[d] = expf(-(float)(d * d) * 0.125f);

    const int c  = tid & 63;
    const int j0 = (tid >> 6) * RPT;     // local output row base (0,8,16,24)

    float ap[RPT], af[RPT];
#pragma unroll
    for (int r = 0; r < RPT; ++r) { ap[r] = 0.0f; af[r] = 0.0f; }

    // input tile rows needed: j0 .. j0 + RPT-1 + 2*DMAX  (48 values)
#pragma unroll
    for (int k = 0; k < RPT + 2 * DMAX; ++k) {
        const float xi = tile[(j0 + k) * C + c];
#pragma unroll
        for (int r = 0; r < RPT; ++r) {
            const int d = k - DMAX - r;       // signed offset from output row r
            if (d >= -DMAX && d <= -1) ap[r] = fmaf(wv[-d], xi, ap[r]);
            else if (d >= 1 && d <= DMAX) af[r] = fmaf(wv[d], xi, af[r]);
        }
    }

#pragma unroll
    for (int r = 0; r < RPT; ++r) {
        const int l = l0 + j0 + r;
        const size_t o = ((size_t)l * B + b) * C + c;
        mp[o] = ap[r] / (float)max(l, 1);
        mf[o] = af[r] / (float)max(L - 1 - l, 1);
    }
}

// warp-level softmax + CE over 64 logits (lane holds j=lane and j=lane+32).
// If outp != nullptr also writes softmax probs. Returns (lse - v[label]).
__device__ __forceinline__ float warp_softmax_ce(float v0, float v1, int lane,
                                                 int label, float* outp) {
    float m = fmaxf(v0, v1);
#pragma unroll
    for (int o = 16; o; o >>= 1) m = fmaxf(m, __shfl_xor_sync(0xffffffffu, m, o));
    float e0 = __expf(v0 - m), e1 = __expf(v1 - m);
    float sum = e0 + e1;
#pragma unroll
    for (int o = 16; o; o >>= 1) sum += __shfl_xor_sync(0xffffffffu, sum, o);
    if (outp) {
        const float inv = 1.0f / sum;
        outp[lane]      = e0 * inv;
        outp[lane + 32] = e1 * inv;
    }
    const float lse = m + __logf(sum);
    const float vl  = __shfl_sync(0xffffffffu, (label < 32) ? v0 : v1, label & 31);
    return lse - vl;
}

// ---------------------------------------------------------------------------
// Kernel 2: one CTA per (l,b). Streams the 5 matrices (80 KB) once.
// All partials accumulate in REGISTERS across the 5 matrices; a single
// reduction at the end. No smem ops in the hot loop -> loads pipeline freely.
// Warp w owns rows [8w,8w+8); lane half (0/1) = even/odd row of each pair;
// li = lane&15 owns columns [4li, 4li+4).
// ---------------------------------------------------------------------------

// M @ vcol -> row partials RACC; M^T @ vrow -> col partials CACC
#define PROC(M, VC, VR, RACC, CACC)                                          \
    {                                                                          \
        const float4 vc = *(const float4*)((VC) + (li << 2));                  \
        _Pragma("unroll")                                                      \
        for (int rp = 0; rp < 4; ++rp) {                                       \
            const int r = rbase + (rp << 1);                                   \
            const float4 m = *(const float4*)((M) + (r << 6) + (li << 2));     \
            RACC[rp] = fmaf(m.x, vc.x,                                         \
                       fmaf(m.y, vc.y,                                         \
                       fmaf(m.z, vc.z,                                         \
                       fmaf(m.w, vc.w, RACC[rp]))));                           \
            const float vr = (VR)[r];                                          \
            CACC.x = fmaf(m.x, vr, CACC.x);                                    \
            CACC.y = fmaf(m.y, vr, CACC.y);                                    \
            CACC.z = fmaf(m.z, vr, CACC.z);                                    \
            CACC.w = fmaf(m.w, vr, CACC.w);                                    \
        }                                                                      \
    }

__global__ void __launch_bounds__(256, 4)
main_kernel(const float* __restrict__ f,  const float* __restrict__ s,
            const float* __restrict__ fs, const float* __restrict__ ff,
            const float* __restrict__ ss, const float* __restrict__ fs_t,
            const float* __restrict__ sf_t,
            const int* __restrict__ f_lab, const int* __restrict__ s_lab,
            float* __restrict__ out) {
    const int blk = blockIdx.x;                 // l*B + b
    const size_t voff = (size_t)blk * C;
    const size_t moff = (size_t)blk * (C * C);
    const int tid = threadIdx.x;

    __shared__ __align__(16) float sf0[C], ss0[C];
    __shared__ __align__(16) float v_fmp[C], v_fmf[C], v_smp[C], v_smf[C];
    __shared__ __align__(16) float v_fW[C], v_sW[C];
    __shared__ __align__(16) float accF[C], accS[C];
    __shared__ float lossAcc;

    if (tid < C) {
        const float fv = f[voff + tid];
        const float sv = s[voff + tid];
        sf0[tid] = fv;          ss0[tid] = sv;
        v_fW[tid] = 0.5f * fv;  v_sW[tid] = 0.5f * sv;            // W_S
        v_fmp[tid] = 0.5f * g_fmp[voff + tid];                     // W_T folded
        v_fmf[tid] = 0.5f * g_fmf[voff + tid];
        v_smp[tid] = 0.5f * g_smp[voff + tid];
        v_smf[tid] = 0.5f * g_smf[voff + tid];
    }
    if (tid == 0) lossAcc = 0.0f;
    __syncthreads();

    const int w    = tid >> 5;
    const int lane = tid & 31;
    const int half = lane >> 4;   // 0 or 1
    const int li   = lane & 15;   // column group
    const int rbase = (w << 3) + half;

    float rowF[4] = {0.f, 0.f, 0.f, 0.f};
    float rowS[4] = {0.f, 0.f, 0.f, 0.f};
    float4 colF = make_float4(0.f, 0.f, 0.f, 0.f);
    float4 colS = make_float4(0.f, 0.f, 0.f, 0.f);

    // next_f row: ff@(wT f_mf), fs@(wS s), fs_t@(wT s_mf)
    // next_f col: ff^T@(wT f_mp), sf_t^T@(wT s_mp)
    // next_s row: ss@(wT s_mf), sf_t@(wT f_mf)
    // next_s col: ss^T@(wT s_mp), fs^T@(wS f), fs_t^T@(wT f_mp)
    PROC(ff   + moff, v_fmf, v_fmp, rowF, colF);
    PROC(ss   + moff, v_smf, v_smp, rowS, colS);
    PROC(fs   + moff, v_sW,  v_fW,  rowF, colS);
    PROC(fs_t + moff, v_smf, v_fmp, rowF, colS);
    PROC(sf_t + moff, v_fmf, v_smp, rowS, colF);

    // ---- row reduction: sum over 16 li-lanes within each half ----
#pragma unroll
    for (int rp = 0; rp < 4; ++rp) {
#pragma unroll
        for (int o = 8; o; o >>= 1) {
            rowF[rp] += __shfl_xor_sync(0xffffffffu, rowF[rp], o);
            rowS[rp] += __shfl_xor_sync(0xffffffffu, rowS[rp], o);
        }
    }
    if (li == 0) {
#pragma unroll
        for (int rp = 0; rp < 4; ++rp) {
            const int r = rbase + (rp << 1);
            accF[r] = rowF[rp];     // exclusive per row -> plain store
            accS[r] = rowS[rp];
        }
    }
    __syncthreads();

    // ---- col reduction: fold odd half into even, then atomics across warps
    colF.x += __shfl_down_sync(0xffffffffu, colF.x, 16);
    colF.y += __shfl_down_sync(0xffffffffu, colF.y, 16);
    colF.z += __shfl_down_sync(0xffffffffu, colF.z, 16);
    colF.w += __shfl_down_sync(0xffffffffu, colF.w, 16);
    colS.x += __shfl_down_sync(0xffffffffu, colS.x, 16);
    colS.y += __shfl_down_sync(0xffffffffu, colS.y, 16);
    colS.z += __shfl_down_sync(0xffffffffu, colS.z, 16);
    colS.w += __shfl_down_sync(0xffffffffu, colS.w, 16);
    if (half == 0) {
        const int cb = li << 2;
        atomicAdd(&accF[cb + 0], colF.x);
        atomicAdd(&accF[cb + 1], colF.y);
        atomicAdd(&accF[cb + 2], colF.z);
        atomicAdd(&accF[cb + 3], colF.w);
        atomicAdd(&accS[cb + 0], colS.x);
        atomicAdd(&accS[cb + 1], colS.y);
        atomicAdd(&accS[cb + 2], colS.z);
        atomicAdd(&accS[cb + 3], colS.w);
    }
    __syncthreads();

    // ---- epilogue: softmax + CE (old & new logits), outputs, loss partial
    if (w == 0) {
        const int lab = f_lab[blk];
        const float a0 = sf0[lane], a1 = sf0[lane + 32];
        const float ce0 = warp_softmax_ce(a0, a1, lane, lab, nullptr);
        const float n0 = a0 + accF[lane], n1 = a1 + accF[lane + 32];
        const float ce1 = warp_softmax_ce(n0, n1, lane, lab, out + voff);
        if (lane == 0) atomicAdd(&lossAcc, ce0 + ce1);
    } else if (w == 1) {
        const int lab = s_lab[blk];
        const float a0 = ss0[lane], a1 = ss0[lane + 32];
        const float ce0 = warp_softmax_ce(a0, a1, lane, lab, nullptr);
        const float n0 = a0 + accS[lane], n1 = a1 + accS[lane + 32];
        const float ce1 = warp_softmax_ce(n0, n1, lane, lab, out + (size_t)LBC + voff);
        if (lane == 0) atomicAdd(&lossAcc, ce0 + ce1);
    }
    __syncthreads();
    if (tid == 0) atomicAdd(&g_buckets[blk & (NBUCKET - 1)], lossAcc);
}

// ---------------------------------------------------------------------------
// Kernel 3: deterministic bucket reduction -> loss scalar.
// ---------------------------------------------------------------------------
__global__ void loss_finalize(float* __restrict__ out_loss) {
    __shared__ float sm[NBUCKET];
    const int t = threadIdx.x;
    sm[t] = g_buckets[t];
    __syncthreads();
    for (int sct = NBUCKET / 2; sct > 0; sct >>= 1) {
        if (t < sct) sm[t] += sm[t + sct];
        __syncthreads();
    }
    if (t == 0) out_loss[0] = sm[0] * (1.0f / (float)LB);
}

// ---------------------------------------------------------------------------
extern "C" void kernel_launch(void* const* d_in, const int* in_sizes, int n_in,
                              void* d_out, int out_size) {
    const float* f    = (const float*)d_in[0];
    const float* s    = (const float*)d_in[1];
    const float* fs   = (const float*)d_in[2];
    const float* ff   = (const float*)d_in[3];
    const float* ss   = (const float*)d_in[4];
    const float* fs_t = (const float*)d_in[5];
    const float* sf_t = (const float*)d_in[6];
    const int* f_lab  = (const int*)d_in[7];
    const int* s_lab  = (const int*)d_in[8];
    float* out = (float*)d_out;

    dim3 g1(L / TL, B, 2);
    msg_kernel<<<g1, 256>>>(f, s);
    main_kernel<<<LB, 256>>>(f, s, fs, ff, ss, fs_t, sf_t, f_lab, s_lab, out);
    loss_finalize<<<1, NBUCKET>>>(out + (size_t)2 * LBC);
}